// round 9
// baseline (speedup 1.0000x reference)
#include <cuda_runtime.h>
#include <cstdint>

// Problem constants
#define BATCH     64
#define NPER      786432
#define VPER      (NPER / 4)              // 196608 int4 per row
#define LEVELS    256
#define HTHREADS  256
#define BPR       8                       // hist CTAs per row -> 512 CTAs
#define V_PER_CTA (VPER / BPR)            // 24576 int4
#define ITERS     (V_PER_CTA / HTHREADS)  // 96 int4 per thread

// All statically zero; every launch returns them to zero -> graph-replay safe.
__device__ unsigned int g_hist[BATCH * LEVELS];   // per-row histograms
__device__ unsigned int g_cnt[BATCH];             // arrival tickets per row
__device__ unsigned int g_flag[BATCH];            // row-complete flag
__device__ unsigned int g_done[BATCH];            // broadcast-done tickets

// ---------------------------------------------------------------------------
// Round-5 structure (empirical optimum), + __ldcs streaming input loads.
// Co-residency: launch_bounds(256,4), 32KB smem -> >=4 CTAs/SM guaranteed,
// 512 CTAs <= 592 slots -> one wave -> spin cannot deadlock.
// ---------------------------------------------------------------------------
__global__ void __launch_bounds__(HTHREADS, 4)
fused_kernel(const int4* __restrict__ x, float4* __restrict__ out) {
    __shared__ unsigned int sh[LEVELS * 32];   // 32 KB

    #pragma unroll
    for (int i = threadIdx.x; i < LEVELS * 32; i += HTHREADS) sh[i] = 0u;
    __syncthreads();

    const unsigned lane = threadIdx.x & 31u;
    unsigned int hbase = (unsigned int)__cvta_generic_to_shared(sh) + (lane << 2);

    const int b = blockIdx.y;
    const int i = blockIdx.x;
    const int4* __restrict__ blk =
        x + (size_t)b * VPER + (size_t)i * V_PER_CTA;

    #pragma unroll 4
    for (int it = 0; it < ITERS; it++) {
        int4 v = __ldcs(&blk[it * HTHREADS + threadIdx.x]);   // streaming load
        asm volatile("red.shared.add.u32 [%0], %1;"
                     :: "r"(hbase + ((unsigned)v.x << 7)), "r"(1u) : "memory");
        asm volatile("red.shared.add.u32 [%0], %1;"
                     :: "r"(hbase + ((unsigned)v.y << 7)), "r"(1u) : "memory");
        asm volatile("red.shared.add.u32 [%0], %1;"
                     :: "r"(hbase + ((unsigned)v.z << 7)), "r"(1u) : "memory");
        asm volatile("red.shared.add.u32 [%0], %1;"
                     :: "r"(hbase + ((unsigned)v.w << 7)), "r"(1u) : "memory");
    }
    __syncthreads();

    // Reduce the 32 lane-copies of bin t (rotated start -> conflict-free),
    // one spread-address global RED per bin.
    {
        const unsigned t = threadIdx.x;
        unsigned int s = 0;
        #pragma unroll
        for (int c = 0; c < 32; c++) s += sh[t * 32 + ((c + t) & 31u)];
        atomicAdd(&g_hist[(unsigned)b * LEVELS + t], s);
    }

    // ---- Row-completion spin-release ----
    __threadfence();                 // publish this thread's REDG
    __syncthreads();                 // all threads of CTA published
    if (threadIdx.x == 0) {
        unsigned t = atomicAdd(&g_cnt[b], 1u);
        if (t == BPR - 1) atomicExch(&g_flag[b], 1u);   // release row
        while (*(volatile unsigned*)&g_flag[b] == 0u) __nanosleep(64);
    }
    __syncthreads();
    __threadfence();                 // acquire: g_hist row now complete

    // ---- Broadcast bins [i*32, i*32+32) of row b ----
    float* shf = (float*)sh;         // reuse smem
    const unsigned binBase = (unsigned)b * LEVELS + (unsigned)i * 32u;
    if (threadIdx.x < 32) {
        shf[threadIdx.x] = (float)g_hist[binBase + threadIdx.x];
        g_hist[binBase + threadIdx.x] = 0u;   // disjoint slice -> safe reset
    }
    __syncthreads();

    float4* __restrict__ dst =
        out + ((size_t)b * LEVELS + (size_t)i * 32u) * (LEVELS / 4);
    #pragma unroll
    for (int k = threadIdx.x; k < 32 * (LEVELS / 4); k += HTHREADS) {
        float v = shf[k >> 6];
        dst[k] = make_float4(v, v, v, v);
    }

    // last CTA of the row to finish resets the row's sync state
    if (threadIdx.x == 0) {
        __threadfence();
        unsigned d = atomicAdd(&g_done[b], 1u);
        if (d == BPR - 1) {
            g_cnt[b]  = 0u;
            g_flag[b] = 0u;
            g_done[b] = 0u;
            __threadfence();
        }
    }
}

// ---------------------------------------------------------------------------
extern "C" void kernel_launch(void* const* d_in, const int* in_sizes, int n_in,
                              void* d_out, int out_size) {
    const int4* x = (const int4*)d_in[0];
    float4* out = (float4*)d_out;

    dim3 grid(BPR, BATCH);
    fused_kernel<<<grid, HTHREADS>>>(x, out);
}

// round 10
// speedup vs baseline: 1.0006x; 1.0006x over previous
#include <cuda_runtime.h>
#include <cstdint>

// Problem constants
#define BATCH     64
#define NPER      786432
#define VPER      (NPER / 4)              // 196608 int4 per row
#define LEVELS    256
#define HTHREADS  256
#define BPR       8                       // hist CTAs per row -> 512 CTAs
#define V_PER_CTA (VPER / BPR)            // 24576 int4
#define ITERS     (V_PER_CTA / HTHREADS)  // 96 int4 per thread

// All statically zero; every launch returns them to zero -> graph-replay safe.
__device__ unsigned int g_hist[BATCH * LEVELS];   // per-row histograms
__device__ unsigned int g_cnt[BATCH];             // arrival tickets per row
__device__ unsigned int g_flag[BATCH];            // row-complete flag
__device__ unsigned int g_done[BATCH];            // broadcast-done tickets

#define REDS(addr) asm volatile("red.shared.add.u32 [%0], %1;" \
                                :: "r"(addr), "r"(1u) : "memory")

// ---------------------------------------------------------------------------
// Round-5 structure (empirical optimum) + manual 1-deep load prefetch.
// Co-residency: launch_bounds(256,4), 32KB smem -> >=4 CTAs/SM guaranteed,
// 512 CTAs <= 592 slots -> one resident wave -> the flag spin cannot deadlock.
// ---------------------------------------------------------------------------
__global__ void __launch_bounds__(HTHREADS, 4)
fused_kernel(const int4* __restrict__ x, float4* __restrict__ out) {
    __shared__ unsigned int sh[LEVELS * 32];   // 32 KB

    #pragma unroll
    for (int i = threadIdx.x; i < LEVELS * 32; i += HTHREADS) sh[i] = 0u;
    __syncthreads();

    const unsigned lane = threadIdx.x & 31u;
    unsigned int hbase = (unsigned int)__cvta_generic_to_shared(sh) + (lane << 2);

    const int b = blockIdx.y;
    const int i = blockIdx.x;
    const int4* __restrict__ blk =
        x + (size_t)b * VPER + (size_t)i * V_PER_CTA;

    // 1-deep software pipeline: next iteration's LDG is issued BEFORE this
    // value's REDs (loads may precede the clobbered asm; the clobber still
    // keeps every RED ordered and prevents hoisting from below).
    int4 v = blk[threadIdx.x];
    #pragma unroll 4
    for (int it = 0; it < ITERS - 1; it++) {
        int4 nv = blk[(it + 1) * HTHREADS + threadIdx.x];   // prefetch
        REDS(hbase + ((unsigned)v.x << 7));
        REDS(hbase + ((unsigned)v.y << 7));
        REDS(hbase + ((unsigned)v.z << 7));
        REDS(hbase + ((unsigned)v.w << 7));
        v = nv;
    }
    REDS(hbase + ((unsigned)v.x << 7));
    REDS(hbase + ((unsigned)v.y << 7));
    REDS(hbase + ((unsigned)v.z << 7));
    REDS(hbase + ((unsigned)v.w << 7));
    __syncthreads();

    // Reduce the 32 lane-copies of bin t (rotated start -> conflict-free),
    // one spread-address global RED per bin.
    {
        const unsigned t = threadIdx.x;
        unsigned int s = 0;
        #pragma unroll
        for (int c = 0; c < 32; c++) s += sh[t * 32 + ((c + t) & 31u)];
        atomicAdd(&g_hist[(unsigned)b * LEVELS + t], s);
    }

    // ---- Row-completion spin-release ----
    __threadfence();                 // publish this thread's REDG
    __syncthreads();                 // all threads of CTA published
    if (threadIdx.x == 0) {
        unsigned t = atomicAdd(&g_cnt[b], 1u);
        if (t == BPR - 1) atomicExch(&g_flag[b], 1u);   // release row
        while (*(volatile unsigned*)&g_flag[b] == 0u) __nanosleep(64);
    }
    __syncthreads();
    __threadfence();                 // acquire: g_hist row now complete

    // ---- Broadcast bins [i*32, i*32+32) of row b ----
    float* shf = (float*)sh;         // reuse smem
    const unsigned binBase = (unsigned)b * LEVELS + (unsigned)i * 32u;
    if (threadIdx.x < 32) {
        shf[threadIdx.x] = (float)g_hist[binBase + threadIdx.x];
        g_hist[binBase + threadIdx.x] = 0u;   // disjoint slice -> safe reset
    }
    __syncthreads();

    float4* __restrict__ dst =
        out + ((size_t)b * LEVELS + (size_t)i * 32u) * (LEVELS / 4);
    #pragma unroll
    for (int k = threadIdx.x; k < 32 * (LEVELS / 4); k += HTHREADS) {
        float v2 = shf[k >> 6];
        dst[k] = make_float4(v2, v2, v2, v2);
    }

    // last CTA of the row to finish resets the row's sync state
    if (threadIdx.x == 0) {
        __threadfence();
        unsigned d = atomicAdd(&g_done[b], 1u);
        if (d == BPR - 1) {
            g_cnt[b]  = 0u;
            g_flag[b] = 0u;
            g_done[b] = 0u;
            __threadfence();
        }
    }
}

// ---------------------------------------------------------------------------
extern "C" void kernel_launch(void* const* d_in, const int* in_sizes, int n_in,
                              void* d_out, int out_size) {
    const int4* x = (const int4*)d_in[0];
    float4* out = (float4*)d_out;

    dim3 grid(BPR, BATCH);
    fused_kernel<<<grid, HTHREADS>>>(x, out);
}

// round 11
// speedup vs baseline: 1.2758x; 1.2751x over previous
#include <cuda_runtime.h>
#include <cstdint>

// Problem constants
#define BATCH     64
#define NPER      786432
#define VPER      (NPER / 4)              // 196608 int4 per row
#define LEVELS    256
#define HTHREADS  256
#define BPR       8                       // hist CTAs per row -> 512 CTAs total
#define V_PER_CTA (VPER / BPR)            // 24576 int4
#define ITERS     (V_PER_CTA / HTHREADS)  // 96 int4 per thread

// All statically zero; every launch returns them to zero -> graph-replay safe.
__device__ unsigned int g_hist[BATCH * LEVELS];   // per-row histograms
__device__ unsigned int g_cnt[BATCH];             // arrival tickets per row
__device__ unsigned int g_flag[BATCH];            // row-complete flag
__device__ unsigned int g_done[BATCH];            // broadcast-done tickets

// ---------------------------------------------------------------------------
// Single fused kernel. grid = (BPR, BATCH), 256 threads.
// __launch_bounds__(256, 4) guarantees >=4 CTAs/SM resident (regs<=64,
// smem 32KB -> 7/SM, threads -> 8/SM), so all 512 CTAs are one co-resident
// wave and the cross-CTA spin below cannot deadlock.
//
// Phase 1 (hist): lane-private smem counter copies sh[v*32+lane] (bank==lane,
//   conflict-free), red.shared increments (no return, no dependent chain),
//   reduce 32 copies, one global RED per bin into g_hist.
// Phase 2 (sync): per-row ticket; last CTA of the row raises g_flag[b].
// Phase 3 (bcast): CTA i of row b broadcasts bins [i*32, i*32+32) to out,
//   zeroes its own g_hist entries; last CTA to finish resets the row counters.
// ---------------------------------------------------------------------------
__global__ void __launch_bounds__(HTHREADS, 4)
fused_kernel(const int4* __restrict__ x, float4* __restrict__ out) {
    __shared__ unsigned int sh[LEVELS * 32];   // 32 KB

    #pragma unroll
    for (int i = threadIdx.x; i < LEVELS * 32; i += HTHREADS) sh[i] = 0u;
    __syncthreads();

    const unsigned lane = threadIdx.x & 31u;
    unsigned int hbase = (unsigned int)__cvta_generic_to_shared(sh) + (lane << 2);

    const int b = blockIdx.y;
    const int i = blockIdx.x;
    const int4* __restrict__ blk =
        x + (size_t)b * VPER + (size_t)i * V_PER_CTA;

    #pragma unroll 4
    for (int it = 0; it < ITERS; it++) {
        int4 v = blk[it * HTHREADS + threadIdx.x];
        asm volatile("red.shared.add.u32 [%0], %1;"
                     :: "r"(hbase + ((unsigned)v.x << 7)), "r"(1u) : "memory");
        asm volatile("red.shared.add.u32 [%0], %1;"
                     :: "r"(hbase + ((unsigned)v.y << 7)), "r"(1u) : "memory");
        asm volatile("red.shared.add.u32 [%0], %1;"
                     :: "r"(hbase + ((unsigned)v.z << 7)), "r"(1u) : "memory");
        asm volatile("red.shared.add.u32 [%0], %1;"
                     :: "r"(hbase + ((unsigned)v.w << 7)), "r"(1u) : "memory");
    }
    __syncthreads();

    // Reduce the 32 lane-copies of bin t (rotated start -> conflict-free),
    // one spread-address global RED per bin.
    {
        const unsigned t = threadIdx.x;
        unsigned int s = 0;
        #pragma unroll
        for (int c = 0; c < 32; c++) s += sh[t * 32 + ((c + t) & 31u)];
        atomicAdd(&g_hist[(unsigned)b * LEVELS + t], s);
    }

    // ---- Phase 2: row-completion sync ----
    __threadfence();                 // publish this thread's REDG
    __syncthreads();                 // all threads of CTA published
    if (threadIdx.x == 0) {
        unsigned t = atomicAdd(&g_cnt[b], 1u);
        if (t == BPR - 1) atomicExch(&g_flag[b], 1u);   // release row
        while (*(volatile unsigned*)&g_flag[b] == 0u) __nanosleep(64);
    }
    __syncthreads();
    __threadfence();                 // acquire: g_hist row now complete

    // ---- Phase 3: broadcast bins [i*32, i*32+32) of row b ----
    float* shf = (float*)sh;         // reuse smem
    const unsigned binBase = (unsigned)b * LEVELS + (unsigned)i * 32u;
    if (threadIdx.x < 32)
        shf[threadIdx.x] = (float)g_hist[binBase + threadIdx.x];
    __syncthreads();

    float4* __restrict__ dst =
        out + ((size_t)b * LEVELS + (size_t)i * 32u) * (LEVELS / 4);
    #pragma unroll
    for (int k = threadIdx.x; k < 32 * (LEVELS / 4); k += HTHREADS) {
        float v = shf[k >> 6];
        dst[k] = make_float4(v, v, v, v);
    }

    // reset this CTA's own g_hist entries (sole reader was this CTA)
    if (threadIdx.x < 32) g_hist[binBase + threadIdx.x] = 0u;

    // last CTA of the row to finish resets the row's sync state
    if (threadIdx.x == 0) {
        __threadfence();
        unsigned d = atomicAdd(&g_done[b], 1u);
        if (d == BPR - 1) {
            g_cnt[b]  = 0u;
            g_flag[b] = 0u;
            g_done[b] = 0u;
            __threadfence();
        }
    }
}

// ---------------------------------------------------------------------------
extern "C" void kernel_launch(void* const* d_in, const int* in_sizes, int n_in,
                              void* d_out, int out_size) {
    const int4* x = (const int4*)d_in[0];
    float4* out = (float4*)d_out;

    dim3 grid(BPR, BATCH);
    fused_kernel<<<grid, HTHREADS>>>(x, out);
}